// round 15
// baseline (speedup 1.0000x reference)
#include <cuda_runtime.h>

#define BATCH 64
#define NN 512
#define NDIAG 1023
#define NEGV  (-1e30f)
#define INV_LN2 1.44269504088896340736f
#define LN2F    0.69314718055994530942f
#define SSTR 20     // stage row stride in floats (16 used): conflict-free LDS.128

// Diagonal-major layout for DP outputs: (k, i) -> k*NN + i.
__device__ float g_f[(size_t)BATCH * NDIAG * NN];      // forward DP (log2 domain)
__device__ float g_b[(size_t)BATCH * NDIAG * NN];      // backward DP MINUS d (log2)
__device__ float g_max;                                // global logit max (log2)

__device__ __forceinline__ float ex2f(float x) {
    float y; asm("ex2.approx.ftz.f32 %0, %1;" : "=f"(y) : "f"(x)); return y;
}
__device__ __forceinline__ float lg2f(float x) {
    float y; asm("lg2.approx.ftz.f32 %0, %1;" : "=f"(y) : "f"(x)); return y;
}

__device__ __forceinline__ float lse_cell(float dg, float up, float lf, float dcur) {
    float hi1 = fmaxf(dg, up);
    float lo1 = fminf(dg, up);
    float m   = fmaxf(hi1, lf);
    float o2  = fminf(hi1, lf);
    float s = ex2f(lo1 - m) + ex2f(o2 - m);   // third term is 2^0 = 1
    return dcur + m + lg2f(1.0f + s);
}

// ---------------------------------------------------------------------------
// Cooperative stage loader: for round base diag kbase, fetch d(i, kbase+p-i)
// for all 512 rows x 8 phases, scaled by 1/ln2. 8 lanes per row -> coalesced.
// Out-of-range cols clamp in-allocation; consumed only by invalid cells.
// ---------------------------------------------------------------------------
template<bool BWD>
__device__ __forceinline__ void stage_fetch(const float* __restrict__ Db,
                                            int kbase, int t, float* vals) {
    int p = t & 7;
    int r0 = t >> 3;            // 0..31
#pragma unroll
    for (int q = 0; q < 16; q++) {
        int r = r0 + 32 * q;    // DP row
        int c = kbase + p - r;  // DP col
        int rg = BWD ? (511 - r) : r;
        int cg = BWD ? (511 - c) : c;
        cg = min(max(cg, 0), 511);
        vals[q] = Db[rg * NN + cg] * INV_LN2;
    }
}

// Write loader values into the transposed stage: value for (row r, phase lp)
// lands at stageT[r>>1][2*lp + (r&1)], so consumer thread t = r>>1 finds its
// 8 (dE,dO) pairs as 16 contiguous floats -> 4x LDS.128.
__device__ __forceinline__ void stage_put(float (*stageT)[SSTR], int t,
                                          const float* vals) {
    int lp = t & 7, lr = t >> 3;
    int base = (lr >> 1) * 0 + 0;  (void)base;
#pragma unroll
    for (int q = 0; q < 16; q++) {
        int r = lr + 32 * q;
        stageT[r >> 1][2 * lp + (r & 1)] = vals[q];
    }
}

// ---------------------------------------------------------------------------
// Wavefront DP: 256 threads, thread t owns rows (2t, 2t+1). Odd-row cell uses
// register inputs only; even-row cell gets the neighbor's odd-row history
// (vO1, vO2) via TWO warp shuffles — no smem on the common path. The 8
// warp-boundary values cross through a tiny parity-double-buffered edge
// array (lane31 writes slot (k+1)&1, lane0 reads slot k&1), fully ordered by
// the existing per-diag __syncthreads: no race, no spin. D comes from the
// double-buffered transposed smem stage, consumed as 4x LDS.128 per round.
// One CTA per (batch, direction). Backward CTAs write (val - d).
// ---------------------------------------------------------------------------
template<bool BWD>
__device__ __forceinline__ void dp_impl(int b, const float* __restrict__ D,
                                        float2 (*edge)[9],
                                        float (*stageT)[256][SSTR]) {
    const float* Db = D + (size_t)b * NN * NN;
    float* out = (BWD ? g_b : g_f) + (size_t)b * NDIAG * NN;
    int t = threadIdx.x;
    int lane = t & 31, w = t >> 5;
    int iE = 2 * t;                   // even row; odd row = iE + 1

    {   // stage round 0
        float v0[16];
        stage_fetch<BWD>(Db, 0, t, v0);
        stage_put(stageT[0], t, v0);
    }
    __syncthreads();

    float vE1 = NEGV, vE2 = NEGV;     // even row at diag k-1, k-2
    float vO1 = NEGV, vO2 = NEGV;     // odd  row at diag k-1, k-2

    for (int tt = 0; tt < 128; tt++) {
        float vals[16];
        stage_fetch<BWD>(Db, 8 * (tt + 1), t, vals);   // next round, in flight
        const int sb = tt & 1;
        float4 dreg[4];
#pragma unroll
        for (int j = 0; j < 4; j++)
            dreg[j] = *(const float4*)&stageT[sb][t][4 * j];
        const float* dv = (const float*)dreg;
#pragma unroll
        for (int p = 0; p < 8; p++) {
            int k = tt * 8 + p;                  // k==1023 is a no-op pad
            if (k < NDIAG) {                     // uniform over the block
                float dE = dv[2 * p], dO = dv[2 * p + 1];

                // neighbor (row iE-1) odd-row history: shfl, lane0 from edge
                float upN = __shfl_up_sync(0xffffffffu, vO1, 1);
                float dgN = __shfl_up_sync(0xffffffffu, vO2, 1);
                if (lane == 0) {
                    float2 e = edge[p & 1][w];   // written at diag k-1
                    dgN = e.x; upN = e.y;        // (O(k-2), O(k-1))
                }

                int jE = k - iE;
                float dgE = dgN;
                if (tt == 0 && p == 0 && t == 0) dgE = 0.0f;   // (0,0) seed
                float vE  = lse_cell(dgE, upN, vE1, dE);
                vE = ((unsigned)jE < NN) ? vE : NEGV;

                // odd cell (iE+1, jE-1): all-register inputs
                float vO  = lse_cell(vE2, vE1, vO1, dO);
                vO = ((unsigned)(jE - 1) < NN) ? vO : NEGV;

                if (lane == 31)                  // publish for diag k+1
                    edge[(p + 1) & 1][w + 1] = make_float2(vO1, vO);

                if ((unsigned)jE <= NN) {        // either row in range
                    float2 st;
                    st.x = BWD ? (vE - dE) : vE;
                    st.y = BWD ? (vO - dO) : vO;
                    *(float2*)(out + (size_t)k * NN + iE) = st;
                }
                vE2 = vE1; vE1 = vE;
                vO2 = vO1; vO1 = vO;
            }
            if (p < 7) __syncthreads();
        }
        stage_put(stageT[sb ^ 1], t, vals);      // publish next round's stage
        __syncthreads();                         // orders p=7 edge + flip
    }
}

__global__ void __launch_bounds__(256) dp_kernel(const float* __restrict__ D) {
    __shared__ float2 edge[2][9];            // [diag parity][warp+1]; [.,0]=NEG
    __shared__ float stageT[2][256][SSTR];   // transposed double-buffered stage
    int bx = blockIdx.x;
    int b = bx >> 1, dir = bx & 1;
    if (threadIdx.x < 18)
        ((float2*)edge)[threadIdx.x] = make_float2(NEGV, NEGV);
    __syncthreads();
    if (dir) dp_impl<true>(b, D, edge, stageT);
    else     dp_impl<false>(b, D, edge, stageT);
}

// ---------------------------------------------------------------------------
// Global max: every path passes through the corner cell, so
// max logit = f(N-1, M-1) maximized over batches.
// ---------------------------------------------------------------------------
__global__ void max_kernel() {
    int t = threadIdx.x;   // 32 threads
    float m = -3.4e38f;
    for (int b = t; b < BATCH; b += 32)
        m = fmaxf(m, g_f[(size_t)b * NDIAG * NN + (size_t)1022 * NN + 511]);
#pragma unroll
    for (int o = 16; o > 0; o >>= 1)
        m = fmaxf(m, __shfl_xor_sync(0xffffffffu, m, o));
    if (t == 0) g_max = m;
}

// ---------------------------------------------------------------------------
// Combine + finish fused: out = (f2 + (b2-d2) - max2) * ln2, de-diagonalized
// to row-major via a padded smem tile.
// ---------------------------------------------------------------------------
__global__ void __launch_bounds__(256) combine_kernel(float* __restrict__ out) {
    __shared__ float tile[32][257];
    int b = blockIdx.y;
    int k0 = blockIdx.x * 32;
    const float* fd = g_f + (size_t)b * NDIAG * NN;
    const float* bd = g_b + (size_t)b * NDIAG * NN;
    float* ob = out + (size_t)b * NN * NN;
    int tid = threadIdx.x, lane = tid & 31, w = tid >> 5;
    float mx = g_max;

    for (int ih = 0; ih < 2; ih++) {
        int ibase = ih * 256;
        for (int kk = 0; kk < 32; kk++) {
            int k = k0 + kk;
            int i = ibase + tid;
            int j = k - i;
            float v = 0.0f;
            if (j >= 0 && j < NN) {
                int a = k * NN + i;
                v = (fd[a] + bd[(1022 - k) * NN + (511 - i)] - mx) * LN2F;
            }
            tile[kk][tid] = v;
        }
        __syncthreads();
        for (int rr = 0; rr < 32; rr++) {
            int i = ibase + w * 32 + rr;
            int jlo = max(0, k0 - i);
            int jhi = min(NN - 1, k0 + 31 - i);
            int j = jlo + lane;
            if (j <= jhi) {
                int kk = i + j - k0;
                ob[(size_t)i * NN + j] = tile[kk][i - ibase];
            }
        }
        __syncthreads();
    }
}

extern "C" void kernel_launch(void* const* d_in, const int* in_sizes, int n_in,
                              void* d_out, int out_size) {
    const float* d = (const float*)d_in[0];
    float* out = (float*)d_out;

    dp_kernel<<<BATCH * 2, 256>>>(d);

    max_kernel<<<1, 32>>>();

    dim3 cgrid(32, BATCH);
    combine_kernel<<<cgrid, 256>>>(out);
}